// round 1
// baseline (speedup 1.0000x reference)
#include <cuda_runtime.h>
#include <math.h>

#define LSEQ   2048
#define DMODEL 1024
#define NHEAD  16
#define HDIM   64

// Scratch (allocation-free rule: __device__ globals)
__device__ float g_q[LSEQ * DMODEL];
__device__ float g_k[LSEQ * DMODEL];
__device__ float g_v[LSEQ * DMODEL];
__device__ float g_att[LSEQ * DMODEL];

// ---------------------------------------------------------------------------
// GEMM: C[M,1024] = X[M,1024] @ W[1024,1024] + bias   (row-major everywhere)
// 128x128 block tile, BK=16, 256 threads, 8x8 microtile per thread.
// ---------------------------------------------------------------------------
__device__ __forceinline__ void gemm_bias_body(
    const float* __restrict__ X, const float* __restrict__ W,
    const float* __restrict__ bias, float* __restrict__ C)
{
    __shared__ float As[16][132];   // A transposed: As[k][m], padded
    __shared__ float Bs[16][132];   // Bs[k][n], padded

    const int bm  = blockIdx.y * 128;
    const int bn  = blockIdx.x * 128;
    const int tid = threadIdx.x;
    const int tx  = tid & 15;
    const int ty  = tid >> 4;

    float acc[8][8];
#pragma unroll
    for (int i = 0; i < 8; i++)
#pragma unroll
        for (int j = 0; j < 8; j++) acc[i][j] = 0.0f;

    for (int k0 = 0; k0 < DMODEL; k0 += 16) {
        // Load A tile 128x16 -> As[k][m]
#pragma unroll
        for (int i = 0; i < 2; i++) {
            int id  = tid + i * 256;
            int row = id >> 2;             // 0..127
            int kq  = (id & 3) << 2;       // 0,4,8,12
            float4 v = *(const float4*)(X + (size_t)(bm + row) * DMODEL + k0 + kq);
            As[kq + 0][row] = v.x;
            As[kq + 1][row] = v.y;
            As[kq + 2][row] = v.z;
            As[kq + 3][row] = v.w;
        }
        // Load B tile 16x128 -> Bs[k][n]
#pragma unroll
        for (int i = 0; i < 2; i++) {
            int id = tid + i * 256;
            int kr = id >> 5;              // 0..15
            int nq = (id & 31) << 2;       // 0..124
            *(float4*)(&Bs[kr][nq]) =
                *(const float4*)(W + (size_t)(k0 + kr) * DMODEL + bn + nq);
        }
        __syncthreads();

#pragma unroll
        for (int kk = 0; kk < 16; kk++) {
            float a[8], b[8];
            *(float4*)(a)     = *(const float4*)(&As[kk][ty * 8]);
            *(float4*)(a + 4) = *(const float4*)(&As[kk][ty * 8 + 4]);
            *(float4*)(b)     = *(const float4*)(&Bs[kk][tx * 8]);
            *(float4*)(b + 4) = *(const float4*)(&Bs[kk][tx * 8 + 4]);
#pragma unroll
            for (int i = 0; i < 8; i++)
#pragma unroll
                for (int j = 0; j < 8; j++)
                    acc[i][j] = fmaf(a[i], b[j], acc[i][j]);
        }
        __syncthreads();
    }

    // Epilogue: += bias, store
#pragma unroll
    for (int i = 0; i < 8; i++) {
        int row = bm + ty * 8 + i;
#pragma unroll
        for (int j = 0; j < 8; j += 4) {
            int col = bn + tx * 8 + j;
            float4 o;
            o.x = acc[i][j + 0] + bias[col + 0];
            o.y = acc[i][j + 1] + bias[col + 1];
            o.z = acc[i][j + 2] + bias[col + 2];
            o.w = acc[i][j + 3] + bias[col + 3];
            *(float4*)(C + (size_t)row * DMODEL + col) = o;
        }
    }
}

// QKV projections batched via blockIdx.z
__global__ __launch_bounds__(256, 1) void qkv_proj_kernel(
    const float* __restrict__ q, const float* __restrict__ k, const float* __restrict__ v,
    const float* __restrict__ wq, const float* __restrict__ bq,
    const float* __restrict__ wk, const float* __restrict__ bk,
    const float* __restrict__ wv, const float* __restrict__ bv)
{
    const float *X, *W, *B;
    float* C;
    if (blockIdx.z == 0)      { X = q; W = wq; B = bq; C = g_q; }
    else if (blockIdx.z == 1) { X = k; W = wk; B = bk; C = g_k; }
    else                      { X = v; W = wv; B = bv; C = g_v; }
    gemm_bias_body(X, W, B, C);
}

__global__ __launch_bounds__(256, 1) void out_proj_kernel(
    const float* __restrict__ wo, const float* __restrict__ bo, float* __restrict__ out)
{
    gemm_bias_body(g_att, wo, bo, out);
}

// ---------------------------------------------------------------------------
// Flash-style attention. One block = (head, 128-query tile).
// 256 threads as 16x16; each thread: 8 score rows x 8 score cols, and
// 8 rows x 4 out-dims of the O accumulator. Online softmax in SMEM.
// Dynamic SMEM layout (floats):
//   Qt [64][132]   (Q^T, scale folded in)
//   Kt [64][132]   (K^T)
//   Vs [128][68]
//   Ps [128][132]  (probabilities)
//   red[128][17]   (row reductions)
//   Mrow[128], Lrow[128], Cf[128]
// ---------------------------------------------------------------------------
#define SM_QT   0
#define SM_KT   (SM_QT + 64 * 132)
#define SM_VS   (SM_KT + 64 * 132)
#define SM_PS   (SM_VS + 128 * 68)
#define SM_RED  (SM_PS + 128 * 132)
#define SM_M    (SM_RED + 128 * 17)
#define SM_L    (SM_M + 128)
#define SM_CF   (SM_L + 128)
#define SM_TOT  (SM_CF + 128)   // 45056 floats = 180224 bytes

extern __shared__ float smdyn[];

__global__ __launch_bounds__(256, 1) void attn_kernel()
{
    float* Qt   = smdyn + SM_QT;
    float* Kt   = smdyn + SM_KT;
    float* Vs   = smdyn + SM_VS;
    float* Ps   = smdyn + SM_PS;
    float* red  = smdyn + SM_RED;
    float* Mrow = smdyn + SM_M;
    float* Lrow = smdyn + SM_L;
    float* Cf   = smdyn + SM_CF;

    const int h   = blockIdx.y;
    const int q0  = blockIdx.x * 128;
    const int tid = threadIdx.x;
    const int tx  = tid & 15;
    const int ty  = tid >> 4;
    const float scale = 0.125f;   // 1/sqrt(64)

    // Load Q tile (scaled) transposed: Qt[d][row]
#pragma unroll
    for (int i = 0; i < 8; i++) {
        int id  = tid + i * 256;
        int row = id >> 4;
        int dq  = (id & 15) << 2;
        float4 val = *(const float4*)(g_q + (size_t)(q0 + row) * DMODEL + h * HDIM + dq);
        Qt[(dq + 0) * 132 + row] = val.x * scale;
        Qt[(dq + 1) * 132 + row] = val.y * scale;
        Qt[(dq + 2) * 132 + row] = val.z * scale;
        Qt[(dq + 3) * 132 + row] = val.w * scale;
    }
    if (tid < 128) { Mrow[tid] = -1e30f; Lrow[tid] = 0.0f; }

    float acc[8][4];
#pragma unroll
    for (int i = 0; i < 8; i++)
#pragma unroll
        for (int j = 0; j < 4; j++) acc[i][j] = 0.0f;

    __syncthreads();

    for (int kt = 0; kt < LSEQ; kt += 128) {
        // Load K (transposed) and V tiles
#pragma unroll
        for (int i = 0; i < 8; i++) {
            int id  = tid + i * 256;
            int row = id >> 4;
            int dq  = (id & 15) << 2;
            float4 kv = *(const float4*)(g_k + (size_t)(kt + row) * DMODEL + h * HDIM + dq);
            Kt[(dq + 0) * 132 + row] = kv.x;
            Kt[(dq + 1) * 132 + row] = kv.y;
            Kt[(dq + 2) * 132 + row] = kv.z;
            Kt[(dq + 3) * 132 + row] = kv.w;
            float4 vv = *(const float4*)(g_v + (size_t)(kt + row) * DMODEL + h * HDIM + dq);
            *(float4*)(&Vs[row * 68 + dq]) = vv;
        }
        __syncthreads();

        // S = (scaled Q) @ K^T : 8x8 per thread
        float s[8][8];
#pragma unroll
        for (int i = 0; i < 8; i++)
#pragma unroll
            for (int j = 0; j < 8; j++) s[i][j] = 0.0f;

#pragma unroll 8
        for (int d = 0; d < 64; d++) {
            float a[8], b[8];
            *(float4*)(a)     = *(const float4*)(&Qt[d * 132 + ty * 8]);
            *(float4*)(a + 4) = *(const float4*)(&Qt[d * 132 + ty * 8 + 4]);
            *(float4*)(b)     = *(const float4*)(&Kt[d * 132 + tx * 8]);
            *(float4*)(b + 4) = *(const float4*)(&Kt[d * 132 + tx * 8 + 4]);
#pragma unroll
            for (int i = 0; i < 8; i++)
#pragma unroll
                for (int j = 0; j < 8; j++)
                    s[i][j] = fmaf(a[i], b[j], s[i][j]);
        }

        // Local row max -> reduction buffer
#pragma unroll
        for (int i = 0; i < 8; i++) {
            float m = s[i][0];
#pragma unroll
            for (int j = 1; j < 8; j++) m = fmaxf(m, s[i][j]);
            red[(ty * 8 + i) * 17 + tx] = m;
        }
        __syncthreads();

        // Per-row: new running max + correction factor
        if (tid < 128) {
            float m = red[tid * 17];
#pragma unroll
            for (int jj = 1; jj < 16; jj++) m = fmaxf(m, red[tid * 17 + jj]);
            float mOld = Mrow[tid];
            float mNew = fmaxf(mOld, m);
            Cf[tid]   = __expf(mOld - mNew);
            Mrow[tid] = mNew;
        }
        __syncthreads();

        // Exponentiate, partial row sums, rescale accumulators
#pragma unroll
        for (int i = 0; i < 8; i++) {
            int r   = ty * 8 + i;
            float m = Mrow[r];
            float ls = 0.0f;
#pragma unroll
            for (int j = 0; j < 8; j++) {
                float p = __expf(s[i][j] - m);
                Ps[r * 132 + tx * 8 + j] = p;
                ls += p;
            }
            red[r * 17 + tx] = ls;
            float cf = Cf[r];
#pragma unroll
            for (int j = 0; j < 4; j++) acc[i][j] *= cf;
        }
        __syncthreads();

        // Update running denominators (independent of PV below)
        if (tid < 128) {
            float ssum = 0.0f;
#pragma unroll
            for (int jj = 0; jj < 16; jj++) ssum += red[tid * 17 + jj];
            Lrow[tid] = Lrow[tid] * Cf[tid] + ssum;
        }

        // O += P @ V : each thread 8 rows x 4 dims
#pragma unroll 4
        for (int j = 0; j < 128; j++) {
            float4 v4 = *(const float4*)(&Vs[j * 68 + tx * 4]);
#pragma unroll
            for (int i = 0; i < 8; i++) {
                float p = Ps[(ty * 8 + i) * 132 + j];
                acc[i][0] = fmaf(p, v4.x, acc[i][0]);
                acc[i][1] = fmaf(p, v4.y, acc[i][1]);
                acc[i][2] = fmaf(p, v4.z, acc[i][2]);
                acc[i][3] = fmaf(p, v4.w, acc[i][3]);
            }
        }
        __syncthreads();   // protects K/V/Ps reuse; publishes Lrow after loop
    }

    // Normalize and write to concat-head layout [L, D]
#pragma unroll
    for (int i = 0; i < 8; i++) {
        int r = ty * 8 + i;
        float inv = 1.0f / Lrow[r];
        float4 o;
        o.x = acc[i][0] * inv;
        o.y = acc[i][1] * inv;
        o.z = acc[i][2] * inv;
        o.w = acc[i][3] * inv;
        *(float4*)(g_att + (size_t)(q0 + r) * DMODEL + h * HDIM + tx * 4) = o;
    }
}

// ---------------------------------------------------------------------------
extern "C" void kernel_launch(void* const* d_in, const int* in_sizes, int n_in,
                              void* d_out, int out_size)
{
    const float* q  = (const float*)d_in[0];
    const float* k  = (const float*)d_in[1];
    const float* v  = (const float*)d_in[2];
    const float* wq = (const float*)d_in[3];
    const float* bq = (const float*)d_in[4];
    const float* wk = (const float*)d_in[5];
    const float* bk = (const float*)d_in[6];
    const float* wv = (const float*)d_in[7];
    const float* bv = (const float*)d_in[8];
    const float* wo = (const float*)d_in[9];
    const float* bo = (const float*)d_in[10];
    float* out = (float*)d_out;

    (void)in_sizes; (void)n_in; (void)out_size;

    // Allow 176KB dynamic smem for the attention kernel (idempotent, not a stream op)
    cudaFuncSetAttribute(attn_kernel, cudaFuncAttributeMaxDynamicSharedMemorySize,
                         SM_TOT * (int)sizeof(float));

    // QKV projections (batched over z)
    {
        dim3 grid(DMODEL / 128, LSEQ / 128, 3);
        qkv_proj_kernel<<<grid, 256>>>(q, k, v, wq, bq, wk, bk, wv, bv);
    }
    // Attention
    {
        dim3 grid(LSEQ / 128, NHEAD);
        attn_kernel<<<grid, 256, SM_TOT * (int)sizeof(float)>>>();
    }
    // Output projection
    {
        dim3 grid(DMODEL / 128, LSEQ / 128);
        out_proj_kernel<<<grid, 256>>>(wo, bo, out);
    }
}

// round 4
// speedup vs baseline: 1.4005x; 1.4005x over previous
#include <cuda_runtime.h>
#include <cuda_bf16.h>
#include <cstdint>
#include <math.h>

#define LSEQ   2048
#define DMODEL 1024
#define NHEAD  16
#define HDIM   64

// ---------------------------------------------------------------------------
// Scratch (__device__ globals; allocation-free rule)
// ---------------------------------------------------------------------------
__device__ float g_q[LSEQ * DMODEL];
__device__ float g_k[LSEQ * DMODEL];
__device__ float g_v[LSEQ * DMODEL];
__device__ float g_att[LSEQ * DMODEL];

__device__ __align__(16) __nv_bfloat16 g_xhi[3][LSEQ * DMODEL];
__device__ __align__(16) __nv_bfloat16 g_xlo[3][LSEQ * DMODEL];
__device__ __align__(16) __nv_bfloat16 g_whi[4][DMODEL * DMODEL];  // transposed: [n][k]
__device__ __align__(16) __nv_bfloat16 g_wlo[4][DMODEL * DMODEL];
__device__ __align__(16) __nv_bfloat16 g_ahi[LSEQ * DMODEL];
__device__ __align__(16) __nv_bfloat16 g_alo[LSEQ * DMODEL];

// ---------------------------------------------------------------------------
// Base-ISA tensor-core helpers (mma.sync + ldmatrix; no 'a'-suffix features)
// ---------------------------------------------------------------------------
__device__ __forceinline__ uint32_t smem_u32(const void* p) {
    uint32_t a;
    asm("{ .reg .u64 t; cvta.to.shared.u64 t, %1; cvt.u32.u64 %0, t; }" : "=r"(a) : "l"(p));
    return a;
}

__device__ __forceinline__ void ldsm_x4(uint32_t* r, uint32_t addr) {
    asm volatile("ldmatrix.sync.aligned.m8n8.x4.shared.b16 {%0,%1,%2,%3}, [%4];"
                 : "=r"(r[0]), "=r"(r[1]), "=r"(r[2]), "=r"(r[3]) : "r"(addr));
}

__device__ __forceinline__ void mma16816(float* c, const uint32_t* a, const uint32_t* b) {
    asm volatile(
        "mma.sync.aligned.m16n8k16.row.col.f32.bf16.bf16.f32 "
        "{%0,%1,%2,%3}, {%4,%5,%6,%7}, {%8,%9}, {%0,%1,%2,%3};"
        : "+f"(c[0]), "+f"(c[1]), "+f"(c[2]), "+f"(c[3])
        : "r"(a[0]), "r"(a[1]), "r"(a[2]), "r"(a[3]), "r"(b[0]), "r"(b[1]));
}

// ---------------------------------------------------------------------------
// bf16 split helpers
// ---------------------------------------------------------------------------
__device__ __forceinline__ void split_bf16(float x, __nv_bfloat16& h, __nv_bfloat16& l) {
    h = __float2bfloat16(x);
    l = __float2bfloat16(x - __bfloat162float(h));
}

// Elementwise split of activations (q,k,v inputs), z-batched
__global__ void conv_x_kernel(const float* __restrict__ q, const float* __restrict__ k,
                              const float* __restrict__ v) {
    int z = blockIdx.z;
    const float* src = (z == 0) ? q : (z == 1) ? k : v;
    __nv_bfloat16* hi = g_xhi[z];
    __nv_bfloat16* lo = g_xlo[z];
    int i = (blockIdx.x * 256 + threadIdx.x) * 4;
    float4 xv = *(const float4*)(src + i);
    union { __nv_bfloat16 b[4]; uint2 u; } H, L;
    split_bf16(xv.x, H.b[0], L.b[0]);
    split_bf16(xv.y, H.b[1], L.b[1]);
    split_bf16(xv.z, H.b[2], L.b[2]);
    split_bf16(xv.w, H.b[3], L.b[3]);
    *(uint2*)(hi + i) = H.u;
    *(uint2*)(lo + i) = L.u;
}

// Split of attention output g_att
__global__ void conv_a_kernel() {
    int i = (blockIdx.x * 256 + threadIdx.x) * 4;
    float4 xv = *(const float4*)(g_att + i);
    union { __nv_bfloat16 b[4]; uint2 u; } H, L;
    split_bf16(xv.x, H.b[0], L.b[0]);
    split_bf16(xv.y, H.b[1], L.b[1]);
    split_bf16(xv.z, H.b[2], L.b[2]);
    split_bf16(xv.w, H.b[3], L.b[3]);
    *(uint2*)(g_ahi + i) = H.u;
    *(uint2*)(g_alo + i) = L.u;
}

// Transpose + split weights: W[k][n] -> Wt[n][k] hi/lo. 32x32 tiles, z-batched over 4.
__global__ void conv_w_kernel(const float* __restrict__ wq, const float* __restrict__ wk,
                              const float* __restrict__ wv, const float* __restrict__ wo) {
    __shared__ float tile[32][33];
    int z = blockIdx.z;
    const float* W = (z == 0) ? wq : (z == 1) ? wk : (z == 2) ? wv : wo;
    __nv_bfloat16* Thi = g_whi[z];
    __nv_bfloat16* Tlo = g_wlo[z];

    int n0 = blockIdx.x * 32;
    int k0 = blockIdx.y * 32;
    int tx = threadIdx.x, ty = threadIdx.y;
#pragma unroll
    for (int i = 0; i < 4; i++)
        tile[ty + i * 8][tx] = W[(size_t)(k0 + ty + i * 8) * DMODEL + n0 + tx];
    __syncthreads();
#pragma unroll
    for (int i = 0; i < 4; i++) {
        float val = tile[tx][ty + i * 8];  // = W[k0+tx][n0+ty+i*8]
        __nv_bfloat16 h, l;
        split_bf16(val, h, l);
        size_t o = (size_t)(n0 + ty + i * 8) * DMODEL + k0 + tx;
        Thi[o] = h;
        Tlo[o] = l;
    }
}

// ---------------------------------------------------------------------------
// HMMA GEMM: C[M,1024] = A @ Wt^T + bias
// A: [m][k] bf16 hi/lo.  Wt: [n][k] bf16 hi/lo (= col-major B for mma .col).
// CTA 128x128, BK=64, 256 threads = 8 warps (2M x 4N), warp tile 64x32.
// 3 passes: Ah*Bh + Ah*Bl + Al*Bh, fp32 accumulate.
// ---------------------------------------------------------------------------
#define GSTRIDE 144                     // bytes per smem row: 64 bf16 + 8 pad
#define GTILE   (128 * GSTRIDE)         // 18432 B
#define OF_AH   0
#define OF_AL   (1 * GTILE)
#define OF_BH   (2 * GTILE)
#define OF_BL   (3 * GTILE)
#define GEMM_SMEM (4 * GTILE)           // 73728 B

extern __shared__ char smraw[];

__device__ __forceinline__ void load_tile(char* dst, const __nv_bfloat16* __restrict__ src,
                                          int row0, int k0, int tid) {
    // 128 rows x 64 bf16 (128B payload, 144B stride)
#pragma unroll
    for (int i = 0; i < 4; i++) {
        int idx = tid + i * 256;       // 0..1023
        int row = idx >> 3;            // 0..127
        int c16 = idx & 7;             // 16B chunk
        uint4 val = *(const uint4*)(src + (size_t)(row0 + row) * DMODEL + k0 + c16 * 8);
        *(uint4*)(dst + row * GSTRIDE + c16 * 16) = val;
    }
}

__device__ __forceinline__ void gemm_mma_body(const __nv_bfloat16* __restrict__ Ah,
                                              const __nv_bfloat16* __restrict__ Al,
                                              const __nv_bfloat16* __restrict__ Bh,
                                              const __nv_bfloat16* __restrict__ Bl,
                                              const float* __restrict__ bias,
                                              float* __restrict__ C) {
    char* sm = smraw;
    const uint32_t smb = smem_u32(sm);
    const int tid  = threadIdx.x;
    const int lane = tid & 31;
    const int wid  = tid >> 5;
    const int wm   = wid >> 2;          // 0..1  (M)
    const int wn   = wid & 3;           // 0..3  (N)
    const int bm   = blockIdx.y * 128;
    const int bn   = blockIdx.x * 128;

    float acc[4][4][4];                 // [mi][ni][creg]
#pragma unroll
    for (int mi = 0; mi < 4; mi++)
#pragma unroll
        for (int ni = 0; ni < 4; ni++)
#pragma unroll
            for (int c = 0; c < 4; c++) acc[mi][ni][c] = 0.0f;

    // ldmatrix per-lane address components
    const uint32_t aRow = lane & 15;
    const uint32_t aCol = (lane >> 4) << 4;                       // 0 or 16 bytes
    const uint32_t bRow = (lane & 7) + ((lane >> 4) << 3);        // n within 16-row group
    const uint32_t bCol = ((lane >> 3) & 1) << 4;                 // 0 or 16 bytes

    const uint32_t aBase = (wm * 64 + aRow) * GSTRIDE + aCol;
    const uint32_t bBase = (wn * 32 + bRow) * GSTRIDE + bCol;

    for (int chunk = 0; chunk < DMODEL / 64; chunk++) {
        const int k0 = chunk * 64;
        load_tile(sm + OF_AH, Ah, bm, k0, tid);
        load_tile(sm + OF_AL, Al, bm, k0, tid);
        load_tile(sm + OF_BH, Bh, bn, k0, tid);
        load_tile(sm + OF_BL, Bl, bn, k0, tid);
        __syncthreads();

#pragma unroll
        for (int kk = 0; kk < 4; kk++) {
            const uint32_t kOff = kk * 32;  // 16 bf16 = 32 bytes
            uint32_t ah[4][4], al[4][4], bh[2][4], bl[2][4];
#pragma unroll
            for (int mi = 0; mi < 4; mi++) {
                ldsm_x4(ah[mi], smb + OF_AH + aBase + mi * (16 * GSTRIDE) + kOff);
                ldsm_x4(al[mi], smb + OF_AL + aBase + mi * (16 * GSTRIDE) + kOff);
            }
#pragma unroll
            for (int nj = 0; nj < 2; nj++) {
                ldsm_x4(bh[nj], smb + OF_BH + bBase + nj * (16 * GSTRIDE) + kOff);
                ldsm_x4(bl[nj], smb + OF_BL + bBase + nj * (16 * GSTRIDE) + kOff);
            }
#pragma unroll
            for (int mi = 0; mi < 4; mi++)
#pragma unroll
                for (int ni = 0; ni < 4; ni++) {
                    const uint32_t* bfh = &bh[ni >> 1][(ni & 1) * 2];
                    const uint32_t* bfl = &bl[ni >> 1][(ni & 1) * 2];
                    mma16816(acc[mi][ni], ah[mi], bfh);
                    mma16816(acc[mi][ni], ah[mi], bfl);
                    mma16816(acc[mi][ni], al[mi], bfh);
                }
        }
        __syncthreads();
    }

    // Epilogue: bias + store
    const int g = lane >> 2;
    const int t = lane & 3;
#pragma unroll
    for (int mi = 0; mi < 4; mi++) {
        const int row = bm + wm * 64 + mi * 16 + g;
#pragma unroll
        for (int ni = 0; ni < 4; ni++) {
            const int col = bn + wn * 32 + ni * 8 + t * 2;
            const float b0 = bias[col], b1 = bias[col + 1];
            float2 o0 = { acc[mi][ni][0] + b0, acc[mi][ni][1] + b1 };
            float2 o1 = { acc[mi][ni][2] + b0, acc[mi][ni][3] + b1 };
            *(float2*)(C + (size_t)row * DMODEL + col)       = o0;
            *(float2*)(C + (size_t)(row + 8) * DMODEL + col) = o1;
        }
    }
}

__global__ __launch_bounds__(256) void qkv_mma_kernel(
    const float* __restrict__ bq, const float* __restrict__ bk, const float* __restrict__ bv)
{
    int z = blockIdx.z;
    const float* bias = (z == 0) ? bq : (z == 1) ? bk : bv;
    float* C = (z == 0) ? g_q : (z == 1) ? g_k : g_v;
    gemm_mma_body(g_xhi[z], g_xlo[z], g_whi[z], g_wlo[z], bias, C);
}

__global__ __launch_bounds__(256) void out_mma_kernel(
    const float* __restrict__ bo, float* __restrict__ out)
{
    gemm_mma_body(g_ahi, g_alo, g_whi[3], g_wlo[3], bo, out);
}

// ---------------------------------------------------------------------------
// Flash-style fp32 attention (known-good from round 1)
// ---------------------------------------------------------------------------
#define SM_QT   0
#define SM_KT   (SM_QT + 64 * 132)
#define SM_VS   (SM_KT + 64 * 132)
#define SM_PS   (SM_VS + 128 * 68)
#define SM_RED  (SM_PS + 128 * 132)
#define SM_M    (SM_RED + 128 * 17)
#define SM_L    (SM_M + 128)
#define SM_CF   (SM_L + 128)
#define SM_TOT  (SM_CF + 128)   // 45056 floats = 180224 bytes

__global__ __launch_bounds__(256, 1) void attn_kernel()
{
    float* smdyn = (float*)smraw;
    float* Qt   = smdyn + SM_QT;
    float* Kt   = smdyn + SM_KT;
    float* Vs   = smdyn + SM_VS;
    float* Ps   = smdyn + SM_PS;
    float* red  = smdyn + SM_RED;
    float* Mrow = smdyn + SM_M;
    float* Lrow = smdyn + SM_L;
    float* Cf   = smdyn + SM_CF;

    const int h   = blockIdx.y;
    const int q0  = blockIdx.x * 128;
    const int tid = threadIdx.x;
    const int tx  = tid & 15;
    const int ty  = tid >> 4;
    const float scale = 0.125f;

#pragma unroll
    for (int i = 0; i < 8; i++) {
        int id  = tid + i * 256;
        int row = id >> 4;
        int dq  = (id & 15) << 2;
        float4 val = *(const float4*)(g_q + (size_t)(q0 + row) * DMODEL + h * HDIM + dq);
        Qt[(dq + 0) * 132 + row] = val.x * scale;
        Qt[(dq + 1) * 132 + row] = val.y * scale;
        Qt[(dq + 2) * 132 + row] = val.z * scale;
        Qt[(dq + 3) * 132 + row] = val.w * scale;
    }
    if (tid < 128) { Mrow[tid] = -1e30f; Lrow[tid] = 0.0f; }

    float acc[8][4];
#pragma unroll
    for (int i = 0; i < 8; i++)
#pragma unroll
        for (int j = 0; j < 4; j++) acc[i][j] = 0.0f;

    __syncthreads();

    for (int kt = 0; kt < LSEQ; kt += 128) {
#pragma unroll
        for (int i = 0; i < 8; i++) {
            int id  = tid + i * 256;
            int row = id >> 4;
            int dq  = (id & 15) << 2;
            float4 kv = *(const float4*)(g_k + (size_t)(kt + row) * DMODEL + h * HDIM + dq);
            Kt[(dq + 0) * 132 + row] = kv.x;
            Kt[(dq + 1) * 132 + row] = kv.y;
            Kt[(dq + 2) * 132 + row] = kv.z;
            Kt[(dq + 3) * 132 + row] = kv.w;
            float4 vv = *(const float4*)(g_v + (size_t)(kt + row) * DMODEL + h * HDIM + dq);
            *(float4*)(&Vs[row * 68 + dq]) = vv;
        }
        __syncthreads();

        float s[8][8];
#pragma unroll
        for (int i = 0; i < 8; i++)
#pragma unroll
            for (int j = 0; j < 8; j++) s[i][j] = 0.0f;

#pragma unroll 8
        for (int d = 0; d < 64; d++) {
            float a[8], b[8];
            *(float4*)(a)     = *(const float4*)(&Qt[d * 132 + ty * 8]);
            *(float4*)(a + 4) = *(const float4*)(&Qt[d * 132 + ty * 8 + 4]);
            *(float4*)(b)     = *(const float4*)(&Kt[d * 132 + tx * 8]);
            *(float4*)(b + 4) = *(const float4*)(&Kt[d * 132 + tx * 8 + 4]);
#pragma unroll
            for (int i = 0; i < 8; i++)
#pragma unroll
                for (int j = 0; j < 8; j++)
                    s[i][j] = fmaf(a[i], b[j], s[i][j]);
        }

#pragma unroll
        for (int i = 0; i < 8; i++) {
            float m = s[i][0];
#pragma unroll
            for (int j = 1; j < 8; j++) m = fmaxf(m, s[i][j]);
            red[(ty * 8 + i) * 17 + tx] = m;
        }
        __syncthreads();

        if (tid < 128) {
            float m = red[tid * 17];
#pragma unroll
            for (int jj = 1; jj < 16; jj++) m = fmaxf(m, red[tid * 17 + jj]);
            float mOld = Mrow[tid];
            float mNew = fmaxf(mOld, m);
            Cf[tid]   = __expf(mOld - mNew);
            Mrow[tid] = mNew;
        }
        __syncthreads();

#pragma unroll
        for (int i = 0; i < 8; i++) {
            int r   = ty * 8 + i;
            float m = Mrow[r];
            float ls = 0.0f;
#pragma unroll
            for (int j = 0; j < 8; j++) {
                float p = __expf(s[i][j] - m);
                Ps[r * 132 + tx * 8 + j] = p;
                ls += p;
            }
            red[r * 17 + tx] = ls;
            float cf = Cf[r];
#pragma unroll
            for (int j = 0; j < 4; j++) acc[i][j] *= cf;
        }
        __syncthreads();

        if (tid < 128) {
            float ssum = 0.0f;
#pragma unroll
            for (int jj = 0; jj < 16; jj++) ssum += red[tid * 17 + jj];
            Lrow[tid] = Lrow[tid] * Cf[tid] + ssum;
        }

#pragma unroll 4
        for (int j = 0; j < 128; j++) {
            float4 v4 = *(const float4*)(&Vs[j * 68 + tx * 4]);
#pragma unroll
            for (int i = 0; i < 8; i++) {
                float p = Ps[(ty * 8 + i) * 132 + j];
                acc[i][0] = fmaf(p, v4.x, acc[i][0]);
                acc[i][1] = fmaf(p, v4.y, acc[i][1]);
                acc[i][2] = fmaf(p, v4.z, acc[i][2]);
                acc[i][3] = fmaf(p, v4.w, acc[i][3]);
            }
        }
        __syncthreads();
    }

#pragma unroll
    for (int i = 0; i < 8; i++) {
        int r = ty * 8 + i;
        float inv = 1.0f / Lrow[r];
        float4 o;
        o.x = acc[i][0] * inv;
        o.y = acc[i][1] * inv;
        o.z = acc[i][2] * inv;
        o.w = acc[i][3] * inv;
        *(float4*)(g_att + (size_t)(q0 + r) * DMODEL + h * HDIM + tx * 4) = o;
    }
}

// ---------------------------------------------------------------------------
extern "C" void kernel_launch(void* const* d_in, const int* in_sizes, int n_in,
                              void* d_out, int out_size)
{
    const float* q  = (const float*)d_in[0];
    const float* k  = (const float*)d_in[1];
    const float* v  = (const float*)d_in[2];
    const float* wq = (const float*)d_in[3];
    const float* bq = (const float*)d_in[4];
    const float* wk = (const float*)d_in[5];
    const float* bk = (const float*)d_in[6];
    const float* wv = (const float*)d_in[7];
    const float* bv = (const float*)d_in[8];
    const float* wo = (const float*)d_in[9];
    const float* bo = (const float*)d_in[10];
    float* out = (float*)d_out;

    (void)in_sizes; (void)n_in; (void)out_size;

    cudaFuncSetAttribute(attn_kernel, cudaFuncAttributeMaxDynamicSharedMemorySize,
                         SM_TOT * (int)sizeof(float));
    cudaFuncSetAttribute(qkv_mma_kernel, cudaFuncAttributeMaxDynamicSharedMemorySize, GEMM_SMEM);
    cudaFuncSetAttribute(out_mma_kernel, cudaFuncAttributeMaxDynamicSharedMemorySize, GEMM_SMEM);

    // 1. Split activations (q,k,v) to bf16 hi/lo
    {
        dim3 grid(LSEQ * DMODEL / (256 * 4), 1, 3);
        conv_x_kernel<<<grid, 256>>>(q, k, v);
    }
    // 2. Transpose + split all 4 weights
    {
        dim3 grid(DMODEL / 32, DMODEL / 32, 4);
        conv_w_kernel<<<grid, dim3(32, 8)>>>(wq, wk, wv, wo);
    }
    // 3. QKV projections on tensor cores (HMMA)
    {
        dim3 grid(DMODEL / 128, LSEQ / 128, 3);
        qkv_mma_kernel<<<grid, 256, GEMM_SMEM>>>(bq, bk, bv);
    }
    // 4. Attention (fp32 flash)
    {
        dim3 grid(LSEQ / 128, NHEAD);
        attn_kernel<<<grid, 256, SM_TOT * (int)sizeof(float)>>>();
    }
    // 5. Split attention output
    {
        dim3 grid(LSEQ * DMODEL / (256 * 4));
        conv_a_kernel<<<grid, 256>>>();
    }
    // 6. Output projection on tensor cores (HMMA)
    {
        dim3 grid(DMODEL / 128, LSEQ / 128);
        out_mma_kernel<<<grid, 256, GEMM_SMEM>>>(bo, out);
    }
}

// round 6
// speedup vs baseline: 2.5822x; 1.8438x over previous
#include <cuda_runtime.h>
#include <cuda_bf16.h>
#include <cstdint>
#include <math.h>

#define LSEQ   2048
#define DMODEL 1024
#define NHEAD  16
#define HDIM   64

// ---------------------------------------------------------------------------
// Scratch (__device__ globals; allocation-free rule)
// ---------------------------------------------------------------------------
__device__ float g_q[LSEQ * DMODEL];
__device__ float g_k[LSEQ * DMODEL];
__device__ float g_v[LSEQ * DMODEL];
__device__ float g_att[LSEQ * DMODEL];

__device__ __align__(16) __nv_bfloat16 g_xhi[3][LSEQ * DMODEL];
__device__ __align__(16) __nv_bfloat16 g_xlo[3][LSEQ * DMODEL];
__device__ __align__(16) __nv_bfloat16 g_whi[4][DMODEL * DMODEL];  // transposed: [n][k]
__device__ __align__(16) __nv_bfloat16 g_wlo[4][DMODEL * DMODEL];
__device__ __align__(16) __nv_bfloat16 g_ahi[LSEQ * DMODEL];
__device__ __align__(16) __nv_bfloat16 g_alo[LSEQ * DMODEL];

// ---------------------------------------------------------------------------
// Base-ISA tensor-core helpers (mma.sync + ldmatrix)
// ---------------------------------------------------------------------------
__device__ __forceinline__ uint32_t smem_u32(const void* p) {
    uint32_t a;
    asm("{ .reg .u64 t; cvta.to.shared.u64 t, %1; cvt.u32.u64 %0, t; }" : "=r"(a) : "l"(p));
    return a;
}

__device__ __forceinline__ void ldsm_x4(uint32_t* r, uint32_t addr) {
    asm volatile("ldmatrix.sync.aligned.m8n8.x4.shared.b16 {%0,%1,%2,%3}, [%4];"
                 : "=r"(r[0]), "=r"(r[1]), "=r"(r[2]), "=r"(r[3]) : "r"(addr));
}

__device__ __forceinline__ void ldsm_x4_t(uint32_t* r, uint32_t addr) {
    asm volatile("ldmatrix.sync.aligned.m8n8.x4.trans.shared.b16 {%0,%1,%2,%3}, [%4];"
                 : "=r"(r[0]), "=r"(r[1]), "=r"(r[2]), "=r"(r[3]) : "r"(addr));
}

__device__ __forceinline__ void mma16816(float* c, const uint32_t* a, const uint32_t* b) {
    asm volatile(
        "mma.sync.aligned.m16n8k16.row.col.f32.bf16.bf16.f32 "
        "{%0,%1,%2,%3}, {%4,%5,%6,%7}, {%8,%9}, {%0,%1,%2,%3};"
        : "+f"(c[0]), "+f"(c[1]), "+f"(c[2]), "+f"(c[3])
        : "r"(a[0]), "r"(a[1]), "r"(a[2]), "r"(a[3]), "r"(b[0]), "r"(b[1]));
}

// ---------------------------------------------------------------------------
// bf16 split helpers
// ---------------------------------------------------------------------------
__device__ __forceinline__ void split_bf16(float x, __nv_bfloat16& h, __nv_bfloat16& l) {
    h = __float2bfloat16(x);
    l = __float2bfloat16(x - __bfloat162float(h));
}

// pack two floats into bf16x2 hi + bf16x2 lo (residual)
__device__ __forceinline__ void pack_pair(float a, float b, uint32_t& hi, uint32_t& lo) {
    __nv_bfloat162 h = __float22bfloat162_rn(make_float2(a, b));
    float ra = a - __bfloat162float(h.x);
    float rb = b - __bfloat162float(h.y);
    __nv_bfloat162 l = __float22bfloat162_rn(make_float2(ra, rb));
    hi = *reinterpret_cast<uint32_t*>(&h);
    lo = *reinterpret_cast<uint32_t*>(&l);
}

// Elementwise split of activations (q,k,v inputs), z-batched
__global__ void conv_x_kernel(const float* __restrict__ q, const float* __restrict__ k,
                              const float* __restrict__ v) {
    int z = blockIdx.z;
    const float* src = (z == 0) ? q : (z == 1) ? k : v;
    __nv_bfloat16* hi = g_xhi[z];
    __nv_bfloat16* lo = g_xlo[z];
    int i = (blockIdx.x * 256 + threadIdx.x) * 4;
    float4 xv = *(const float4*)(src + i);
    union { __nv_bfloat16 b[4]; uint2 u; } H, L;
    split_bf16(xv.x, H.b[0], L.b[0]);
    split_bf16(xv.y, H.b[1], L.b[1]);
    split_bf16(xv.z, H.b[2], L.b[2]);
    split_bf16(xv.w, H.b[3], L.b[3]);
    *(uint2*)(hi + i) = H.u;
    *(uint2*)(lo + i) = L.u;
}

// Split of attention output g_att
__global__ void conv_a_kernel() {
    int i = (blockIdx.x * 256 + threadIdx.x) * 4;
    float4 xv = *(const float4*)(g_att + i);
    union { __nv_bfloat16 b[4]; uint2 u; } H, L;
    split_bf16(xv.x, H.b[0], L.b[0]);
    split_bf16(xv.y, H.b[1], L.b[1]);
    split_bf16(xv.z, H.b[2], L.b[2]);
    split_bf16(xv.w, H.b[3], L.b[3]);
    *(uint2*)(g_ahi + i) = H.u;
    *(uint2*)(g_alo + i) = L.u;
}

// Transpose + split weights: W[k][n] -> Wt[n][k] hi/lo. 32x32 tiles, z-batched over 4.
__global__ void conv_w_kernel(const float* __restrict__ wq, const float* __restrict__ wk,
                              const float* __restrict__ wv, const float* __restrict__ wo) {
    __shared__ float tile[32][33];
    int z = blockIdx.z;
    const float* W = (z == 0) ? wq : (z == 1) ? wk : (z == 2) ? wv : wo;
    __nv_bfloat16* Thi = g_whi[z];
    __nv_bfloat16* Tlo = g_wlo[z];

    int n0 = blockIdx.x * 32;
    int k0 = blockIdx.y * 32;
    int tx = threadIdx.x, ty = threadIdx.y;
#pragma unroll
    for (int i = 0; i < 4; i++)
        tile[ty + i * 8][tx] = W[(size_t)(k0 + ty + i * 8) * DMODEL + n0 + tx];
    __syncthreads();
#pragma unroll
    for (int i = 0; i < 4; i++) {
        float val = tile[tx][ty + i * 8];  // = W[k0+tx][n0+ty+i*8]
        __nv_bfloat16 h, l;
        split_bf16(val, h, l);
        size_t o = (size_t)(n0 + ty + i * 8) * DMODEL + k0 + tx;
        Thi[o] = h;
        Tlo[o] = l;
    }
}

// ---------------------------------------------------------------------------
// HMMA GEMM (unchanged from round 4, passing): C = A @ Wt^T + bias
// ---------------------------------------------------------------------------
#define GSTRIDE 144                     // bytes per smem row: 64 bf16 + 8 pad
#define GTILE   (128 * GSTRIDE)         // 18432 B
#define OF_AH   0
#define OF_AL   (1 * GTILE)
#define OF_BH   (2 * GTILE)
#define OF_BL   (3 * GTILE)
#define GEMM_SMEM (4 * GTILE)           // 73728 B

extern __shared__ char smraw[];

__device__ __forceinline__ void load_tile(char* dst, const __nv_bfloat16* __restrict__ src,
                                          int row0, int k0, int tid) {
#pragma unroll
    for (int i = 0; i < 4; i++) {
        int idx = tid + i * 256;       // 0..1023
        int row = idx >> 3;            // 0..127
        int c16 = idx & 7;             // 16B chunk
        uint4 val = *(const uint4*)(src + (size_t)(row0 + row) * DMODEL + k0 + c16 * 8);
        *(uint4*)(dst + row * GSTRIDE + c16 * 16) = val;
    }
}

__device__ __forceinline__ void gemm_mma_body(const __nv_bfloat16* __restrict__ Ah,
                                              const __nv_bfloat16* __restrict__ Al,
                                              const __nv_bfloat16* __restrict__ Bh,
                                              const __nv_bfloat16* __restrict__ Bl,
                                              const float* __restrict__ bias,
                                              float* __restrict__ C) {
    char* sm = smraw;
    const uint32_t smb = smem_u32(sm);
    const int tid  = threadIdx.x;
    const int lane = tid & 31;
    const int wid  = tid >> 5;
    const int wm   = wid >> 2;
    const int wn   = wid & 3;
    const int bm   = blockIdx.y * 128;
    const int bn   = blockIdx.x * 128;

    float acc[4][4][4];
#pragma unroll
    for (int mi = 0; mi < 4; mi++)
#pragma unroll
        for (int ni = 0; ni < 4; ni++)
#pragma unroll
            for (int c = 0; c < 4; c++) acc[mi][ni][c] = 0.0f;

    const uint32_t aRow = lane & 15;
    const uint32_t aCol = (lane >> 4) << 4;
    const uint32_t bRow = (lane & 7) + ((lane >> 4) << 3);
    const uint32_t bCol = ((lane >> 3) & 1) << 4;

    const uint32_t aBase = (wm * 64 + aRow) * GSTRIDE + aCol;
    const uint32_t bBase = (wn * 32 + bRow) * GSTRIDE + bCol;

    for (int chunk = 0; chunk < DMODEL / 64; chunk++) {
        const int k0 = chunk * 64;
        load_tile(sm + OF_AH, Ah, bm, k0, tid);
        load_tile(sm + OF_AL, Al, bm, k0, tid);
        load_tile(sm + OF_BH, Bh, bn, k0, tid);
        load_tile(sm + OF_BL, Bl, bn, k0, tid);
        __syncthreads();

#pragma unroll
        for (int kk = 0; kk < 4; kk++) {
            const uint32_t kOff = kk * 32;
            uint32_t ah[4][4], al[4][4], bh[2][4], bl[2][4];
#pragma unroll
            for (int mi = 0; mi < 4; mi++) {
                ldsm_x4(ah[mi], smb + OF_AH + aBase + mi * (16 * GSTRIDE) + kOff);
                ldsm_x4(al[mi], smb + OF_AL + aBase + mi * (16 * GSTRIDE) + kOff);
            }
#pragma unroll
            for (int nj = 0; nj < 2; nj++) {
                ldsm_x4(bh[nj], smb + OF_BH + bBase + nj * (16 * GSTRIDE) + kOff);
                ldsm_x4(bl[nj], smb + OF_BL + bBase + nj * (16 * GSTRIDE) + kOff);
            }
#pragma unroll
            for (int mi = 0; mi < 4; mi++)
#pragma unroll
                for (int ni = 0; ni < 4; ni++) {
                    const uint32_t* bfh = &bh[ni >> 1][(ni & 1) * 2];
                    const uint32_t* bfl = &bl[ni >> 1][(ni & 1) * 2];
                    mma16816(acc[mi][ni], ah[mi], bfh);
                    mma16816(acc[mi][ni], ah[mi], bfl);
                    mma16816(acc[mi][ni], al[mi], bfh);
                }
        }
        __syncthreads();
    }

    const int g = lane >> 2;
    const int t = lane & 3;
#pragma unroll
    for (int mi = 0; mi < 4; mi++) {
        const int row = bm + wm * 64 + mi * 16 + g;
#pragma unroll
        for (int ni = 0; ni < 4; ni++) {
            const int col = bn + wn * 32 + ni * 8 + t * 2;
            const float b0 = bias[col], b1 = bias[col + 1];
            float2 o0 = { acc[mi][ni][0] + b0, acc[mi][ni][1] + b1 };
            float2 o1 = { acc[mi][ni][2] + b0, acc[mi][ni][3] + b1 };
            *(float2*)(C + (size_t)row * DMODEL + col)       = o0;
            *(float2*)(C + (size_t)(row + 8) * DMODEL + col) = o1;
        }
    }
}

__global__ __launch_bounds__(256) void qkv_mma_kernel(
    const float* __restrict__ bq, const float* __restrict__ bk, const float* __restrict__ bv)
{
    int z = blockIdx.z;
    const float* bias = (z == 0) ? bq : (z == 1) ? bk : bv;
    float* C = (z == 0) ? g_q : (z == 1) ? g_k : g_v;
    gemm_mma_body(g_xhi[z], g_xlo[z], g_whi[z], g_wlo[z], bias, C);
}

__global__ __launch_bounds__(256) void out_mma_kernel(
    const float* __restrict__ bo, float* __restrict__ out)
{
    gemm_mma_body(g_ahi, g_alo, g_whi[3], g_wlo[3], bo, out);
}

// ---------------------------------------------------------------------------
// HMMA flash attention.
// Block = (q-tile 128, head). 256 threads = 8 warps, warp w owns q-rows
// [w*16, w*16+16). Per k-tile of 128 keys: S = Qs·K^T (3-pass split HMMA),
// online softmax in registers (quad shfl reductions), P stays in registers
// as A-fragments for O += P·V (3-pass split HMMA, V via ldmatrix.trans).
// ---------------------------------------------------------------------------
#define AT_QH 0
#define AT_QL (1 * GTILE)
#define AT_KH (2 * GTILE)
#define AT_KL (3 * GTILE)
#define AT_VH (4 * GTILE)
#define AT_VL (5 * GTILE)
#define ATTN_SMEM (6 * GTILE)   // 110592 B

__global__ __launch_bounds__(256, 1) void attn_mma_kernel()
{
    char* sm = smraw;
    const uint32_t smb = smem_u32(sm);
    const int tid  = threadIdx.x;
    const int lane = tid & 31;
    const int w    = tid >> 5;
    const int g    = lane >> 2;
    const int t    = lane & 3;
    const int h    = blockIdx.y;
    const int q0   = blockIdx.x * 128;

    // Load Q tile (scale 1/8 folded in, exact) -> bf16 hi/lo smem
#pragma unroll
    for (int i = 0; i < 8; i++) {
        int idx = tid + i * 256;          // 0..2047
        int row = idx >> 4;               // 0..127
        int ch  = idx & 15;               // 4-elem chunk of 64 dims
        float4 val = *(const float4*)(g_q + (size_t)(q0 + row) * DMODEL + h * HDIM + ch * 4);
        val.x *= 0.125f; val.y *= 0.125f; val.z *= 0.125f; val.w *= 0.125f;
        union { __nv_bfloat16 b[4]; uint2 u; } H, L;
        split_bf16(val.x, H.b[0], L.b[0]);
        split_bf16(val.y, H.b[1], L.b[1]);
        split_bf16(val.z, H.b[2], L.b[2]);
        split_bf16(val.w, H.b[3], L.b[3]);
        *(uint2*)(sm + AT_QH + row * GSTRIDE + ch * 8) = H.u;
        *(uint2*)(sm + AT_QL + row * GSTRIDE + ch * 8) = L.u;
    }

    // Fragment address bases
    const uint32_t aOff = (uint32_t)(w * 16 + (lane & 15)) * GSTRIDE + ((lane >> 4) << 4);
    const uint32_t bOff = (uint32_t)((lane & 7) + ((lane >> 4) << 3)) * GSTRIDE
                        + (((lane >> 3) & 1) << 4);
    const uint32_t vOff = (uint32_t)((lane & 7) + (((lane >> 3) & 1) << 3)) * GSTRIDE
                        + ((lane >> 4) << 4);

    float o[8][4];
#pragma unroll
    for (int i = 0; i < 8; i++)
#pragma unroll
        for (int c = 0; c < 4; c++) o[i][c] = 0.0f;
    float m0 = -1e30f, m1 = -1e30f, l0 = 0.0f, l1 = 0.0f;

    __syncthreads();

    for (int kt0 = 0; kt0 < LSEQ; kt0 += 128) {
        // Load K and V tiles -> bf16 hi/lo smem
#pragma unroll
        for (int i = 0; i < 8; i++) {
            int idx = tid + i * 256;
            int row = idx >> 4;
            int ch  = idx & 15;
            const size_t go = (size_t)(kt0 + row) * DMODEL + h * HDIM + ch * 4;
            float4 kv = *(const float4*)(g_k + go);
            float4 vv = *(const float4*)(g_v + go);
            union { __nv_bfloat16 b[4]; uint2 u; } KH, KL, VH, VL;
            split_bf16(kv.x, KH.b[0], KL.b[0]);
            split_bf16(kv.y, KH.b[1], KL.b[1]);
            split_bf16(kv.z, KH.b[2], KL.b[2]);
            split_bf16(kv.w, KH.b[3], KL.b[3]);
            split_bf16(vv.x, VH.b[0], VL.b[0]);
            split_bf16(vv.y, VH.b[1], VL.b[1]);
            split_bf16(vv.z, VH.b[2], VL.b[2]);
            split_bf16(vv.w, VH.b[3], VL.b[3]);
            uint32_t so = row * GSTRIDE + ch * 8;
            *(uint2*)(sm + AT_KH + so) = KH.u;
            *(uint2*)(sm + AT_KL + so) = KL.u;
            *(uint2*)(sm + AT_VH + so) = VH.u;
            *(uint2*)(sm + AT_VL + so) = VL.u;
        }
        __syncthreads();

        // ---- S = Qs @ K^T (3-pass) ----
        float s[16][4];
#pragma unroll
        for (int j = 0; j < 16; j++)
#pragma unroll
            for (int c = 0; c < 4; c++) s[j][c] = 0.0f;

#pragma unroll
        for (int ks = 0; ks < 4; ks++) {
            const uint32_t kOff = ks * 32;
            uint32_t qh[4], ql[4];
            ldsm_x4(qh, smb + AT_QH + aOff + kOff);
            ldsm_x4(ql, smb + AT_QL + aOff + kOff);
#pragma unroll
            for (int j = 0; j < 8; j++) {
                uint32_t kh[4], kl[4];
                const uint32_t ka = bOff + j * (16 * GSTRIDE) + kOff;
                ldsm_x4(kh, smb + AT_KH + ka);
                ldsm_x4(kl, smb + AT_KL + ka);
                mma16816(s[2 * j],     qh, &kh[0]);
                mma16816(s[2 * j],     qh, &kl[0]);
                mma16816(s[2 * j],     ql, &kh[0]);
                mma16816(s[2 * j + 1], qh, &kh[2]);
                mma16816(s[2 * j + 1], qh, &kl[2]);
                mma16816(s[2 * j + 1], ql, &kh[2]);
            }
        }

        // ---- online softmax (rows g and g+8 of this warp's 16-row tile) ----
        float mx0 = -1e30f, mx1 = -1e30f;
#pragma unroll
        for (int j = 0; j < 16; j++) {
            mx0 = fmaxf(mx0, fmaxf(s[j][0], s[j][1]));
            mx1 = fmaxf(mx1, fmaxf(s[j][2], s[j][3]));
        }
        mx0 = fmaxf(mx0, __shfl_xor_sync(0xffffffffu, mx0, 1));
        mx0 = fmaxf(mx0, __shfl_xor_sync(0xffffffffu, mx0, 2));
        mx1 = fmaxf(mx1, __shfl_xor_sync(0xffffffffu, mx1, 1));
        mx1 = fmaxf(mx1, __shfl_xor_sync(0xffffffffu, mx1, 2));

        const float nm0 = fmaxf(m0, mx0);
        const float nm1 = fmaxf(m1, mx1);
        const float cf0 = __expf(m0 - nm0);
        const float cf1 = __expf(m1 - nm1);
        m0 = nm0; m1 = nm1;

        float sum0 = 0.0f, sum1 = 0.0f;
#pragma unroll
        for (int j = 0; j < 16; j++) {
            float p0 = __expf(s[j][0] - m0);
            float p1 = __expf(s[j][1] - m0);
            float p2 = __expf(s[j][2] - m1);
            float p3 = __expf(s[j][3] - m1);
            s[j][0] = p0; s[j][1] = p1; s[j][2] = p2; s[j][3] = p3;
            sum0 += p0 + p1;
            sum1 += p2 + p3;
        }
        sum0 += __shfl_xor_sync(0xffffffffu, sum0, 1);
        sum0 += __shfl_xor_sync(0xffffffffu, sum0, 2);
        sum1 += __shfl_xor_sync(0xffffffffu, sum1, 1);
        sum1 += __shfl_xor_sync(0xffffffffu, sum1, 2);
        l0 = l0 * cf0 + sum0;
        l1 = l1 * cf1 + sum1;

#pragma unroll
        for (int dt = 0; dt < 8; dt++) {
            o[dt][0] *= cf0; o[dt][1] *= cf0;
            o[dt][2] *= cf1; o[dt][3] *= cf1;
        }

        // ---- O += P @ V (3-pass; P regs are already A-fragments) ----
#pragma unroll
        for (int kt = 0; kt < 8; kt++) {
            uint32_t ph[4], pl[4];
            pack_pair(s[2 * kt][0],     s[2 * kt][1],     ph[0], pl[0]);
            pack_pair(s[2 * kt][2],     s[2 * kt][3],     ph[1], pl[1]);
            pack_pair(s[2 * kt + 1][0], s[2 * kt + 1][1], ph[2], pl[2]);
            pack_pair(s[2 * kt + 1][2], s[2 * kt + 1][3], ph[3], pl[3]);
#pragma unroll
            for (int dp = 0; dp < 4; dp++) {
                uint32_t vh[4], vl[4];
                const uint32_t va = vOff + kt * (16 * GSTRIDE) + dp * 32;
                ldsm_x4_t(vh, smb + AT_VH + va);
                ldsm_x4_t(vl, smb + AT_VL + va);
                mma16816(o[2 * dp],     ph, &vh[0]);
                mma16816(o[2 * dp],     pl, &vh[0]);
                mma16816(o[2 * dp],     ph, &vl[0]);
                mma16816(o[2 * dp + 1], ph, &vh[2]);
                mma16816(o[2 * dp + 1], pl, &vh[2]);
                mma16816(o[2 * dp + 1], ph, &vl[2]);
            }
        }
        __syncthreads();   // K/V/(Q none) smem reuse next iteration
    }

    // Normalize and write to concat-head layout [L, D]
    const float inv0 = 1.0f / l0;
    const float inv1 = 1.0f / l1;
    const int row = q0 + w * 16 + g;
#pragma unroll
    for (int dt = 0; dt < 8; dt++) {
        const int col = h * HDIM + dt * 8 + t * 2;
        *(float2*)(g_att + (size_t)row * DMODEL + col) =
            make_float2(o[dt][0] * inv0, o[dt][1] * inv0);
        *(float2*)(g_att + (size_t)(row + 8) * DMODEL + col) =
            make_float2(o[dt][2] * inv1, o[dt][3] * inv1);
    }
}

// ---------------------------------------------------------------------------
extern "C" void kernel_launch(void* const* d_in, const int* in_sizes, int n_in,
                              void* d_out, int out_size)
{
    const float* q  = (const float*)d_in[0];
    const float* k  = (const float*)d_in[1];
    const float* v  = (const float*)d_in[2];
    const float* wq = (const float*)d_in[3];
    const float* bq = (const float*)d_in[4];
    const float* wk = (const float*)d_in[5];
    const float* bk = (const float*)d_in[6];
    const float* wv = (const float*)d_in[7];
    const float* bv = (const float*)d_in[8];
    const float* wo = (const float*)d_in[9];
    const float* bo = (const float*)d_in[10];
    float* out = (float*)d_out;

    (void)in_sizes; (void)n_in; (void)out_size;

    cudaFuncSetAttribute(qkv_mma_kernel, cudaFuncAttributeMaxDynamicSharedMemorySize, GEMM_SMEM);
    cudaFuncSetAttribute(out_mma_kernel, cudaFuncAttributeMaxDynamicSharedMemorySize, GEMM_SMEM);
    cudaFuncSetAttribute(attn_mma_kernel, cudaFuncAttributeMaxDynamicSharedMemorySize, ATTN_SMEM);

    // 1. Split activations (q,k,v) to bf16 hi/lo
    {
        dim3 grid(LSEQ * DMODEL / (256 * 4), 1, 3);
        conv_x_kernel<<<grid, 256>>>(q, k, v);
    }
    // 2. Transpose + split all 4 weights
    {
        dim3 grid(DMODEL / 32, DMODEL / 32, 4);
        conv_w_kernel<<<grid, dim3(32, 8)>>>(wq, wk, wv, wo);
    }
    // 3. QKV projections on tensor cores (HMMA)
    {
        dim3 grid(DMODEL / 128, LSEQ / 128, 3);
        qkv_mma_kernel<<<grid, 256, GEMM_SMEM>>>(bq, bk, bv);
    }
    // 4. Attention (HMMA flash, 3-pass split)
    {
        dim3 grid(LSEQ / 128, NHEAD);
        attn_mma_kernel<<<grid, 256, ATTN_SMEM>>>();
    }
    // 5. Split attention output
    {
        dim3 grid(LSEQ * DMODEL / (256 * 4));
        conv_a_kernel<<<grid, 256>>>();
    }
    // 6. Output projection on tensor cores (HMMA)
    {
        dim3 grid(DMODEL / 128, LSEQ / 128);
        out_mma_kernel<<<grid, 256, GEMM_SMEM>>>(bo, out);
    }
}

// round 7
// speedup vs baseline: 2.6942x; 1.0434x over previous
#include <cuda_runtime.h>
#include <cuda_bf16.h>
#include <cstdint>
#include <math.h>

#define LSEQ   2048
#define DMODEL 1024
#define NHEAD  16
#define HDIM   64

// ---------------------------------------------------------------------------
// Scratch (__device__ globals; allocation-free rule)
// ---------------------------------------------------------------------------
__device__ __align__(16) __nv_bfloat16 g_xhi[3][LSEQ * DMODEL];
__device__ __align__(16) __nv_bfloat16 g_xlo[3][LSEQ * DMODEL];
__device__ __align__(16) __nv_bfloat16 g_whi[4][DMODEL * DMODEL];  // transposed: [n][k]
__device__ __align__(16) __nv_bfloat16 g_wlo[4][DMODEL * DMODEL];
// projected Q (pre-scaled), K, V and attention output, bf16 hi/lo
__device__ __align__(16) __nv_bfloat16 g_qh[LSEQ * DMODEL];
__device__ __align__(16) __nv_bfloat16 g_ql[LSEQ * DMODEL];
__device__ __align__(16) __nv_bfloat16 g_kh[LSEQ * DMODEL];
__device__ __align__(16) __nv_bfloat16 g_kl[LSEQ * DMODEL];
__device__ __align__(16) __nv_bfloat16 g_vh[LSEQ * DMODEL];
__device__ __align__(16) __nv_bfloat16 g_vl[LSEQ * DMODEL];
__device__ __align__(16) __nv_bfloat16 g_ahi[LSEQ * DMODEL];
__device__ __align__(16) __nv_bfloat16 g_alo[LSEQ * DMODEL];

// ---------------------------------------------------------------------------
// Base-ISA tensor-core + async-copy helpers
// ---------------------------------------------------------------------------
__device__ __forceinline__ uint32_t smem_u32(const void* p) {
    uint32_t a;
    asm("{ .reg .u64 t; cvta.to.shared.u64 t, %1; cvt.u32.u64 %0, t; }" : "=r"(a) : "l"(p));
    return a;
}
__device__ __forceinline__ void ldsm_x4(uint32_t* r, uint32_t addr) {
    asm volatile("ldmatrix.sync.aligned.m8n8.x4.shared.b16 {%0,%1,%2,%3}, [%4];"
                 : "=r"(r[0]), "=r"(r[1]), "=r"(r[2]), "=r"(r[3]) : "r"(addr));
}
__device__ __forceinline__ void ldsm_x4_t(uint32_t* r, uint32_t addr) {
    asm volatile("ldmatrix.sync.aligned.m8n8.x4.trans.shared.b16 {%0,%1,%2,%3}, [%4];"
                 : "=r"(r[0]), "=r"(r[1]), "=r"(r[2]), "=r"(r[3]) : "r"(addr));
}
__device__ __forceinline__ void mma16816(float* c, const uint32_t* a, const uint32_t* b) {
    asm volatile(
        "mma.sync.aligned.m16n8k16.row.col.f32.bf16.bf16.f32 "
        "{%0,%1,%2,%3}, {%4,%5,%6,%7}, {%8,%9}, {%0,%1,%2,%3};"
        : "+f"(c[0]), "+f"(c[1]), "+f"(c[2]), "+f"(c[3])
        : "r"(a[0]), "r"(a[1]), "r"(a[2]), "r"(a[3]), "r"(b[0]), "r"(b[1]));
}
__device__ __forceinline__ void cp16(uint32_t dst, const void* src) {
    asm volatile("cp.async.cg.shared.global [%0], [%1], 16;" :: "r"(dst), "l"(src));
}
#define CP_COMMIT() asm volatile("cp.async.commit_group;" ::: "memory")
#define CP_WAIT0()  asm volatile("cp.async.wait_group 0;" ::: "memory")
#define CP_WAIT1()  asm volatile("cp.async.wait_group 1;" ::: "memory")

// ---------------------------------------------------------------------------
// bf16 split helpers
// ---------------------------------------------------------------------------
__device__ __forceinline__ void split_bf16(float x, __nv_bfloat16& h, __nv_bfloat16& l) {
    h = __float2bfloat16(x);
    l = __float2bfloat16(x - __bfloat162float(h));
}
__device__ __forceinline__ void pack_pair(float a, float b, uint32_t& hi, uint32_t& lo) {
    __nv_bfloat162 h = __float22bfloat162_rn(make_float2(a, b));
    float ra = a - __bfloat162float(h.x);
    float rb = b - __bfloat162float(h.y);
    __nv_bfloat162 l = __float22bfloat162_rn(make_float2(ra, rb));
    hi = *reinterpret_cast<uint32_t*>(&h);
    lo = *reinterpret_cast<uint32_t*>(&l);
}

// Elementwise split of activations (q,k,v inputs), z-batched
__global__ void conv_x_kernel(const float* __restrict__ q, const float* __restrict__ k,
                              const float* __restrict__ v) {
    int z = blockIdx.z;
    const float* src = (z == 0) ? q : (z == 1) ? k : v;
    __nv_bfloat16* hi = g_xhi[z];
    __nv_bfloat16* lo = g_xlo[z];
    int i = (blockIdx.x * 256 + threadIdx.x) * 4;
    float4 xv = *(const float4*)(src + i);
    union { __nv_bfloat16 b[4]; uint2 u; } H, L;
    split_bf16(xv.x, H.b[0], L.b[0]);
    split_bf16(xv.y, H.b[1], L.b[1]);
    split_bf16(xv.z, H.b[2], L.b[2]);
    split_bf16(xv.w, H.b[3], L.b[3]);
    *(uint2*)(hi + i) = H.u;
    *(uint2*)(lo + i) = L.u;
}

// Transpose + split weights: W[k][n] -> Wt[n][k] hi/lo. 32x32 tiles, z-batched over 4.
__global__ void conv_w_kernel(const float* __restrict__ wq, const float* __restrict__ wk,
                              const float* __restrict__ wv, const float* __restrict__ wo) {
    __shared__ float tile[32][33];
    int z = blockIdx.z;
    const float* W = (z == 0) ? wq : (z == 1) ? wk : (z == 2) ? wv : wo;
    __nv_bfloat16* Thi = g_whi[z];
    __nv_bfloat16* Tlo = g_wlo[z];

    int n0 = blockIdx.x * 32;
    int k0 = blockIdx.y * 32;
    int tx = threadIdx.x, ty = threadIdx.y;
#pragma unroll
    for (int i = 0; i < 4; i++)
        tile[ty + i * 8][tx] = W[(size_t)(k0 + ty + i * 8) * DMODEL + n0 + tx];
    __syncthreads();
#pragma unroll
    for (int i = 0; i < 4; i++) {
        float val = tile[tx][ty + i * 8];
        __nv_bfloat16 h, l;
        split_bf16(val, h, l);
        size_t o = (size_t)(n0 + ty + i * 8) * DMODEL + k0 + tx;
        Thi[o] = h;
        Tlo[o] = l;
    }
}

// ---------------------------------------------------------------------------
// HMMA GEMM with cp.async double buffering.
// C = A @ Wt^T + bias; 3-pass split; CTA 128x128, BK=64, 256 threads.
// SPLIT=1: write bf16 hi/lo (optionally scaled); SPLIT=0: write fp32.
// ---------------------------------------------------------------------------
#define GSTRIDE 144                     // bytes per smem row: 64 bf16 + 8 pad
#define GTILE   (128 * GSTRIDE)         // 18432 B
#define OF_AH   0
#define OF_AL   (1 * GTILE)
#define OF_BH   (2 * GTILE)
#define OF_BL   (3 * GTILE)
#define GBUF    (4 * GTILE)
#define GEMM_SMEM (2 * GBUF)            // 147456 B

extern __shared__ char smraw[];

__device__ __forceinline__ void issue_tile(uint32_t dst, const __nv_bfloat16* __restrict__ src,
                                           int row0, int k0, int tid) {
#pragma unroll
    for (int i = 0; i < 4; i++) {
        int idx = tid + i * 256;       // 0..1023
        int row = idx >> 3;            // 0..127
        int c16 = idx & 7;             // 16B chunk
        cp16(dst + row * GSTRIDE + c16 * 16,
             src + (size_t)(row0 + row) * DMODEL + k0 + c16 * 8);
    }
}

template <int SPLIT>
__device__ __forceinline__ void gemm_mma_body(
    const __nv_bfloat16* __restrict__ Ah, const __nv_bfloat16* __restrict__ Al,
    const __nv_bfloat16* __restrict__ Bh, const __nv_bfloat16* __restrict__ Bl,
    const float* __restrict__ bias, float oscale,
    float* __restrict__ C, __nv_bfloat16* __restrict__ Chi, __nv_bfloat16* __restrict__ Clo)
{
    const uint32_t smb = smem_u32(smraw);
    const int tid  = threadIdx.x;
    const int lane = tid & 31;
    const int wid  = tid >> 5;
    const int wm   = wid >> 2;
    const int wn   = wid & 3;
    const int bm   = blockIdx.y * 128;
    const int bn   = blockIdx.x * 128;

    float acc[4][4][4];
#pragma unroll
    for (int mi = 0; mi < 4; mi++)
#pragma unroll
        for (int ni = 0; ni < 4; ni++)
#pragma unroll
            for (int c = 0; c < 4; c++) acc[mi][ni][c] = 0.0f;

    const uint32_t aBase = (uint32_t)(wm * 64 + (lane & 15)) * GSTRIDE + ((lane >> 4) << 4);
    const uint32_t bBase = (uint32_t)(wn * 32 + (lane & 7) + ((lane >> 4) << 3)) * GSTRIDE
                         + (((lane >> 3) & 1) << 4);

    // prologue: stage chunk 0
    issue_tile(smb + OF_AH, Ah, bm, 0, tid);
    issue_tile(smb + OF_AL, Al, bm, 0, tid);
    issue_tile(smb + OF_BH, Bh, bn, 0, tid);
    issue_tile(smb + OF_BL, Bl, bn, 0, tid);
    CP_COMMIT();

    for (int chunk = 0; chunk < DMODEL / 64; chunk++) {
        const uint32_t cb = smb + (chunk & 1) * GBUF;
        if (chunk < DMODEL / 64 - 1) {
            const uint32_t nb = smb + ((chunk + 1) & 1) * GBUF;
            const int k1 = (chunk + 1) * 64;
            issue_tile(nb + OF_AH, Ah, bm, k1, tid);
            issue_tile(nb + OF_AL, Al, bm, k1, tid);
            issue_tile(nb + OF_BH, Bh, bn, k1, tid);
            issue_tile(nb + OF_BL, Bl, bn, k1, tid);
            CP_COMMIT();
            CP_WAIT1();
        } else {
            CP_WAIT0();
        }
        __syncthreads();

#pragma unroll
        for (int kk = 0; kk < 4; kk++) {
            const uint32_t kOff = kk * 32;
            uint32_t ah[4][4], al[4][4], bh[2][4], bl[2][4];
#pragma unroll
            for (int mi = 0; mi < 4; mi++) {
                ldsm_x4(ah[mi], cb + OF_AH + aBase + mi * (16 * GSTRIDE) + kOff);
                ldsm_x4(al[mi], cb + OF_AL + aBase + mi * (16 * GSTRIDE) + kOff);
            }
#pragma unroll
            for (int nj = 0; nj < 2; nj++) {
                ldsm_x4(bh[nj], cb + OF_BH + bBase + nj * (16 * GSTRIDE) + kOff);
                ldsm_x4(bl[nj], cb + OF_BL + bBase + nj * (16 * GSTRIDE) + kOff);
            }
#pragma unroll
            for (int mi = 0; mi < 4; mi++)
#pragma unroll
                for (int ni = 0; ni < 4; ni++) {
                    const uint32_t* bfh = &bh[ni >> 1][(ni & 1) * 2];
                    const uint32_t* bfl = &bl[ni >> 1][(ni & 1) * 2];
                    mma16816(acc[mi][ni], ah[mi], bfh);
                    mma16816(acc[mi][ni], ah[mi], bfl);
                    mma16816(acc[mi][ni], al[mi], bfh);
                }
        }
        __syncthreads();
    }

    const int g = lane >> 2;
    const int t = lane & 3;
#pragma unroll
    for (int mi = 0; mi < 4; mi++) {
        const int row = bm + wm * 64 + mi * 16 + g;
#pragma unroll
        for (int ni = 0; ni < 4; ni++) {
            const int col = bn + wn * 32 + ni * 8 + t * 2;
            const float b0 = bias[col], b1 = bias[col + 1];
            float v0 = acc[mi][ni][0] + b0, v1 = acc[mi][ni][1] + b1;
            float v2 = acc[mi][ni][2] + b0, v3 = acc[mi][ni][3] + b1;
            if (SPLIT) {
                v0 *= oscale; v1 *= oscale; v2 *= oscale; v3 *= oscale;
                uint32_t h0, l0, h1, l1;
                pack_pair(v0, v1, h0, l0);
                pack_pair(v2, v3, h1, l1);
                const size_t o0 = (size_t)row * DMODEL + col;
                const size_t o1 = (size_t)(row + 8) * DMODEL + col;
                *(uint32_t*)(Chi + o0) = h0;
                *(uint32_t*)(Clo + o0) = l0;
                *(uint32_t*)(Chi + o1) = h1;
                *(uint32_t*)(Clo + o1) = l1;
            } else {
                *(float2*)(C + (size_t)row * DMODEL + col)       = make_float2(v0, v1);
                *(float2*)(C + (size_t)(row + 8) * DMODEL + col) = make_float2(v2, v3);
            }
        }
    }
}

__global__ __launch_bounds__(256) void qkv_mma_kernel(
    const float* __restrict__ bq, const float* __restrict__ bk, const float* __restrict__ bv)
{
    int z = blockIdx.z;
    const float* bias = (z == 0) ? bq : (z == 1) ? bk : bv;
    __nv_bfloat16* Chi = (z == 0) ? g_qh : (z == 1) ? g_kh : g_vh;
    __nv_bfloat16* Clo = (z == 0) ? g_ql : (z == 1) ? g_kl : g_vl;
    const float sc = (z == 0) ? 0.125f : 1.0f;   // fold softmax scale into Q (exact)
    gemm_mma_body<1>(g_xhi[z], g_xlo[z], g_whi[z], g_wlo[z], bias, sc, nullptr, Chi, Clo);
}

__global__ __launch_bounds__(256) void out_mma_kernel(
    const float* __restrict__ bo, float* __restrict__ out)
{
    gemm_mma_body<0>(g_ahi, g_alo, g_whi[3], g_wlo[3], bo, 1.0f, out, nullptr, nullptr);
}

// ---------------------------------------------------------------------------
// HMMA flash attention, pre-split inputs + cp.async double-buffered K/V.
// Block = (q-tile 128, head). 8 warps; warp w owns q-rows [w*16, w*16+16).
// ---------------------------------------------------------------------------
#define AT_QH 0
#define AT_QL (1 * GTILE)
#define AT_KV (2 * GTILE)          // 2 buffers x {KH,KL,VH,VL}
#define KV_KH 0
#define KV_KL (1 * GTILE)
#define KV_VH (2 * GTILE)
#define KV_VL (3 * GTILE)
#define KVBUF (4 * GTILE)
#define ATTN_SMEM (AT_KV + 2 * KVBUF)   // 184320 B

__device__ __forceinline__ void issue_kv(uint32_t base, int kt0, int h, int tid) {
#pragma unroll
    for (int i = 0; i < 4; i++) {
        int idx = tid + i * 256;
        int row = idx >> 3;
        int c16 = idx & 7;
        const uint32_t so = row * GSTRIDE + c16 * 16;
        const size_t go = (size_t)(kt0 + row) * DMODEL + h * HDIM + c16 * 8;
        cp16(base + KV_KH + so, g_kh + go);
        cp16(base + KV_KL + so, g_kl + go);
        cp16(base + KV_VH + so, g_vh + go);
        cp16(base + KV_VL + so, g_vl + go);
    }
}

__global__ __launch_bounds__(256, 1) void attn_mma_kernel()
{
    char* sm = smraw;
    const uint32_t smb = smem_u32(sm);
    const int tid  = threadIdx.x;
    const int lane = tid & 31;
    const int w    = tid >> 5;
    const int g    = lane >> 2;
    const int t    = lane & 3;
    const int h    = blockIdx.y;
    const int q0   = blockIdx.x * 128;

    // stage K/V tile 0 (async), then fill Q (plain copies; already scaled+split)
    issue_kv(smb + AT_KV, 0, h, tid);
    CP_COMMIT();

#pragma unroll
    for (int i = 0; i < 4; i++) {
        int idx = tid + i * 256;
        int row = idx >> 3;
        int c16 = idx & 7;
        const uint32_t so = row * GSTRIDE + c16 * 16;
        const size_t go = (size_t)(q0 + row) * DMODEL + h * HDIM + c16 * 8;
        *(uint4*)(sm + AT_QH + so) = *(const uint4*)(g_qh + go);
        *(uint4*)(sm + AT_QL + so) = *(const uint4*)(g_ql + go);
    }

    const uint32_t aOff = (uint32_t)(w * 16 + (lane & 15)) * GSTRIDE + ((lane >> 4) << 4);
    const uint32_t bOff = (uint32_t)((lane & 7) + ((lane >> 4) << 3)) * GSTRIDE
                        + (((lane >> 3) & 1) << 4);
    const uint32_t vOff = (uint32_t)((lane & 7) + (((lane >> 3) & 1) << 3)) * GSTRIDE
                        + ((lane >> 4) << 4);

    float o[8][4];
#pragma unroll
    for (int i = 0; i < 8; i++)
#pragma unroll
        for (int c = 0; c < 4; c++) o[i][c] = 0.0f;
    float m0 = -1e30f, m1 = -1e30f, l0 = 0.0f, l1 = 0.0f;

    for (int it = 0; it < LSEQ / 128; it++) {
        const uint32_t kb = smb + AT_KV + (it & 1) * KVBUF;
        if (it < LSEQ / 128 - 1) {
            issue_kv(smb + AT_KV + ((it + 1) & 1) * KVBUF, (it + 1) * 128, h, tid);
            CP_COMMIT();
            CP_WAIT1();
        } else {
            CP_WAIT0();
        }
        __syncthreads();

        // ---- S = Qs @ K^T (3-pass) ----
        float s[16][4];
#pragma unroll
        for (int j = 0; j < 16; j++)
#pragma unroll
            for (int c = 0; c < 4; c++) s[j][c] = 0.0f;

#pragma unroll
        for (int ks = 0; ks < 4; ks++) {
            const uint32_t kOff = ks * 32;
            uint32_t qh[4], ql[4];
            ldsm_x4(qh, smb + AT_QH + aOff + kOff);
            ldsm_x4(ql, smb + AT_QL + aOff + kOff);
#pragma unroll
            for (int j = 0; j < 8; j++) {
                uint32_t kh[4], kl[4];
                const uint32_t ka = bOff + j * (16 * GSTRIDE) + kOff;
                ldsm_x4(kh, kb + KV_KH + ka);
                ldsm_x4(kl, kb + KV_KL + ka);
                mma16816(s[2 * j],     qh, &kh[0]);
                mma16816(s[2 * j],     qh, &kl[0]);
                mma16816(s[2 * j],     ql, &kh[0]);
                mma16816(s[2 * j + 1], qh, &kh[2]);
                mma16816(s[2 * j + 1], qh, &kl[2]);
                mma16816(s[2 * j + 1], ql, &kh[2]);
            }
        }

        // ---- online softmax ----
        float mx0 = -1e30f, mx1 = -1e30f;
#pragma unroll
        for (int j = 0; j < 16; j++) {
            mx0 = fmaxf(mx0, fmaxf(s[j][0], s[j][1]));
            mx1 = fmaxf(mx1, fmaxf(s[j][2], s[j][3]));
        }
        mx0 = fmaxf(mx0, __shfl_xor_sync(0xffffffffu, mx0, 1));
        mx0 = fmaxf(mx0, __shfl_xor_sync(0xffffffffu, mx0, 2));
        mx1 = fmaxf(mx1, __shfl_xor_sync(0xffffffffu, mx1, 1));
        mx1 = fmaxf(mx1, __shfl_xor_sync(0xffffffffu, mx1, 2));

        const float nm0 = fmaxf(m0, mx0);
        const float nm1 = fmaxf(m1, mx1);
        const float cf0 = __expf(m0 - nm0);
        const float cf1 = __expf(m1 - nm1);
        m0 = nm0; m1 = nm1;

        float sum0 = 0.0f, sum1 = 0.0f;
#pragma unroll
        for (int j = 0; j < 16; j++) {
            float p0 = __expf(s[j][0] - m0);
            float p1 = __expf(s[j][1] - m0);
            float p2 = __expf(s[j][2] - m1);
            float p3 = __expf(s[j][3] - m1);
            s[j][0] = p0; s[j][1] = p1; s[j][2] = p2; s[j][3] = p3;
            sum0 += p0 + p1;
            sum1 += p2 + p3;
        }
        sum0 += __shfl_xor_sync(0xffffffffu, sum0, 1);
        sum0 += __shfl_xor_sync(0xffffffffu, sum0, 2);
        sum1 += __shfl_xor_sync(0xffffffffu, sum1, 1);
        sum1 += __shfl_xor_sync(0xffffffffu, sum1, 2);
        l0 = l0 * cf0 + sum0;
        l1 = l1 * cf1 + sum1;

#pragma unroll
        for (int dt = 0; dt < 8; dt++) {
            o[dt][0] *= cf0; o[dt][1] *= cf0;
            o[dt][2] *= cf1; o[dt][3] *= cf1;
        }

        // ---- O += P @ V (3-pass; P regs are A-fragments) ----
#pragma unroll
        for (int kt = 0; kt < 8; kt++) {
            uint32_t ph[4], pl[4];
            pack_pair(s[2 * kt][0],     s[2 * kt][1],     ph[0], pl[0]);
            pack_pair(s[2 * kt][2],     s[2 * kt][3],     ph[1], pl[1]);
            pack_pair(s[2 * kt + 1][0], s[2 * kt + 1][1], ph[2], pl[2]);
            pack_pair(s[2 * kt + 1][2], s[2 * kt + 1][3], ph[3], pl[3]);
#pragma unroll
            for (int dp = 0; dp < 4; dp++) {
                uint32_t vh[4], vl[4];
                const uint32_t va = vOff + kt * (16 * GSTRIDE) + dp * 32;
                ldsm_x4_t(vh, kb + KV_VH + va);
                ldsm_x4_t(vl, kb + KV_VL + va);
                mma16816(o[2 * dp],     ph, &vh[0]);
                mma16816(o[2 * dp],     pl, &vh[0]);
                mma16816(o[2 * dp],     ph, &vl[0]);
                mma16816(o[2 * dp + 1], ph, &vh[2]);
                mma16816(o[2 * dp + 1], pl, &vh[2]);
                mma16816(o[2 * dp + 1], ph, &vl[2]);
            }
        }
        __syncthreads();
    }

    // Normalize and write split bf16 to concat-head layout [L, D]
    const float inv0 = 1.0f / l0;
    const float inv1 = 1.0f / l1;
    const int row = q0 + w * 16 + g;
#pragma unroll
    for (int dt = 0; dt < 8; dt++) {
        const int col = h * HDIM + dt * 8 + t * 2;
        uint32_t h0, l0u, h1, l1u;
        pack_pair(o[dt][0] * inv0, o[dt][1] * inv0, h0, l0u);
        pack_pair(o[dt][2] * inv1, o[dt][3] * inv1, h1, l1u);
        const size_t o0 = (size_t)row * DMODEL + col;
        const size_t o1 = (size_t)(row + 8) * DMODEL + col;
        *(uint32_t*)(g_ahi + o0) = h0;
        *(uint32_t*)(g_alo + o0) = l0u;
        *(uint32_t*)(g_ahi + o1) = h1;
        *(uint32_t*)(g_alo + o1) = l1u;
    }
}

// ---------------------------------------------------------------------------
extern "C" void kernel_launch(void* const* d_in, const int* in_sizes, int n_in,
                              void* d_out, int out_size)
{
    const float* q  = (const float*)d_in[0];
    const float* k  = (const float*)d_in[1];
    const float* v  = (const float*)d_in[2];
    const float* wq = (const float*)d_in[3];
    const float* bq = (const float*)d_in[4];
    const float* wk = (const float*)d_in[5];
    const float* bk = (const float*)d_in[6];
    const float* wv = (const float*)d_in[7];
    const float* bv = (const float*)d_in[8];
    const float* wo = (const float*)d_in[9];
    const float* bo = (const float*)d_in[10];
    float* out = (float*)d_out;

    (void)in_sizes; (void)n_in; (void)out_size;

    cudaFuncSetAttribute(qkv_mma_kernel, cudaFuncAttributeMaxDynamicSharedMemorySize, GEMM_SMEM);
    cudaFuncSetAttribute(out_mma_kernel, cudaFuncAttributeMaxDynamicSharedMemorySize, GEMM_SMEM);
    cudaFuncSetAttribute(attn_mma_kernel, cudaFuncAttributeMaxDynamicSharedMemorySize, ATTN_SMEM);

    // 1. Split activations (q,k,v) to bf16 hi/lo
    {
        dim3 grid(LSEQ * DMODEL / (256 * 4), 1, 3);
        conv_x_kernel<<<grid, 256>>>(q, k, v);
    }
    // 2. Transpose + split all 4 weights
    {
        dim3 grid(DMODEL / 32, DMODEL / 32, 4);
        conv_w_kernel<<<grid, dim3(32, 8)>>>(wq, wk, wv, wo);
    }
    // 3. QKV projections (HMMA, pipelined) -> bf16 hi/lo, Q pre-scaled
    {
        dim3 grid(DMODEL / 128, LSEQ / 128, 3);
        qkv_mma_kernel<<<grid, 256, GEMM_SMEM>>>(bq, bk, bv);
    }
    // 4. Attention (HMMA flash, pipelined K/V)
    {
        dim3 grid(LSEQ / 128, NHEAD);
        attn_mma_kernel<<<grid, 256, ATTN_SMEM>>>();
    }
    // 5. Output projection (HMMA, pipelined)
    {
        dim3 grid(DMODEL / 128, LSEQ / 128);
        out_mma_kernel<<<grid, 256, GEMM_SMEM>>>(bo, out);
    }
}